// round 12
// baseline (speedup 1.0000x reference)
#include <cuda_runtime.h>
#include <cuda_bf16.h>
#include <cstdint>

#define T_STEPS 512
#define BATCH   512
#define INSZ    300
#define HID     16
#define NG      64
#define NROWS   (T_STEPS*BATCH)     // 262144
#define TILE_M  256
#define NTILES  (NROWS/TILE_M)      // 1024
#define GEMM_BLKS 148
#define SCAN_BLKS 128
#define STRIDE_T (BATCH*NG)
#define B_WORDS (19*64*8)           // 9728 uint32 = 38912 B static smem

__device__ float d_xg[(size_t)(NROWS + 4 * BATCH) * NG];
__device__ unsigned int d_flag[NTILES];

// ---------------- helpers ----------------
__device__ __forceinline__ void mma16816(float* d, uint32_t a0, uint32_t a1, uint32_t a2,
                                         uint32_t a3, uint32_t b0, uint32_t b1) {
    asm volatile(
        "mma.sync.aligned.m16n8k16.row.col.f32.bf16.bf16.f32 "
        "{%0,%1,%2,%3}, {%4,%5,%6,%7}, {%8,%9}, {%0,%1,%2,%3};"
        : "+f"(d[0]), "+f"(d[1]), "+f"(d[2]), "+f"(d[3])
        : "r"(a0), "r"(a1), "r"(a2), "r"(a3), "r"(b0), "r"(b1));
}
__device__ __forceinline__ uint32_t packbf(float lo, float hi) {
    __nv_bfloat162 p = __floats2bfloat162_rn(lo, hi);
    return *reinterpret_cast<uint32_t*>(&p);
}
__device__ __forceinline__ float tanhapx(float x) {
    float y;
    asm("tanh.approx.f32 %0, %1;" : "=f"(y) : "f"(x));
    return y;
}
__device__ __forceinline__ float sigt(float x) {
    return fmaf(tanhapx(0.5f * x), 0.5f, 0.5f);
}
__device__ __forceinline__ float sigx(float x) {
    float e = __expf(-x);
    return __fdividef(1.0f, 1.0f + e);
}
__device__ __forceinline__ unsigned ldacq(const unsigned* p) {
    unsigned v;
    asm volatile("ld.acquire.gpu.global.b32 %0, [%1];" : "=r"(v) : "l"(p) : "memory");
    return v;
}
// wait until steps t0..t0+3 (side) are fully produced
__device__ __forceinline__ void wait4(int t0, int side) {
    const unsigned* f0 = &d_flag[2 * (t0 + 0) + side];
    const unsigned* f1 = &d_flag[2 * (t0 + 1) + side];
    const unsigned* f2 = &d_flag[2 * (t0 + 2) + side];
    const unsigned* f3 = &d_flag[2 * (t0 + 3) + side];
    unsigned v0 = ldacq(f0), v1 = ldacq(f1), v2 = ldacq(f2), v3 = ldacq(f3);
    if ((v0 & v1 & v2 & v3) != 8u) {
        while (ldacq(f0) != 8u) __nanosleep(128);
        while (ldacq(f1) != 8u) __nanosleep(128);
        while (ldacq(f2) != 8u) __nanosleep(128);
        while (ldacq(f3) != 8u) __nanosleep(128);
    }
}

__global__ void zero_flags() {
    int i = blockIdx.x * 256 + threadIdx.x;
    if (i < NTILES) d_flag[i] = 0u;
}

// ---------------- fused: 148 GEMM blocks + 128 scan blocks ----------------
__global__ void __launch_bounds__(256, 2)
fused_kernel(const float* __restrict__ x, const float* __restrict__ W,
             const float* __restrict__ Whh,
             const float* __restrict__ b_ih, const float* __restrict__ b_hh,
             const float* __restrict__ W1, const float* __restrict__ b1,
             const float* __restrict__ W2, const float* __restrict__ b2,
             float* __restrict__ out) {
    __shared__ uint32_t sB[B_WORDS];
    const int tid  = threadIdx.x;
    const int lane = tid & 31;
    const unsigned FULL = 0xffffffffu;

    if (blockIdx.x < GEMM_BLKS) {
        // ================= GEMM block (bf16 mma, A direct from gmem) =================
        const int w  = tid >> 5;
        const int g  = lane >> 2;
        const int tg = lane & 3;

        // B fill (once): W[n][k] fp32 -> bf16x2 fragment-pair layout
        for (int i = tid; i < 19 * 64 * 4; i += 256) {
            int s = i >> 8;
            int n = (i >> 2) & 63;
            int t = i & 3;
            int k0 = 16 * s + 2 * t;
            const float* Wn = W + (size_t)n * INSZ;
            float v0 = (k0     < INSZ) ? Wn[k0]     : 0.0f;
            float v1 = (k0 + 1 < INSZ) ? Wn[k0 + 1] : 0.0f;
            float v2 = (k0 + 8 < INSZ) ? Wn[k0 + 8] : 0.0f;
            float v3 = (k0 + 9 < INSZ) ? Wn[k0 + 9] : 0.0f;
            int base = ((s * 64 + n) * 4 + t) * 2;
            sB[base]     = packbf(v0, v1);
            sB[base + 1] = packbf(v2, v3);
        }
        __syncthreads();

        for (int tile = blockIdx.x; tile < NTILES; tile += GEMM_BLKS) {
            const float* R0 = x + (size_t)(tile * TILE_M + w * 32 + g) * INSZ;
            const float* R1 = R0 + 16 * INSZ;

            float acc[2][8][4];
#pragma unroll
            for (int i = 0; i < 2; i++)
#pragma unroll
                for (int j = 0; j < 8; j++)
#pragma unroll
                    for (int r = 0; r < 4; r++) acc[i][j][r] = 0.0f;

            // prime sl=0 fragments
            float2 fa[2][4], fb[2][4];
            {
                const int k0 = 2 * tg;
#pragma unroll
                for (int i = 0; i < 2; i++) {
                    const float* R = i ? R1 : R0;
                    fa[i][0] = *reinterpret_cast<const float2*>(R + k0);
                    fa[i][1] = *reinterpret_cast<const float2*>(R + 8 * INSZ + k0);
                    fa[i][2] = *reinterpret_cast<const float2*>(R + k0 + 8);
                    fa[i][3] = *reinterpret_cast<const float2*>(R + 8 * INSZ + k0 + 8);
                }
            }

            for (int sl = 0; sl < 19; sl++) {
                if (sl < 18) {
                    const int kn = (sl + 1) * 16 + 2 * tg;
                    const bool okhi = (sl < 17) || (tg < 2);   // sl+1==18: k>=300 masked
#pragma unroll
                    for (int i = 0; i < 2; i++) {
                        const float* R = i ? R1 : R0;
                        fb[i][0] = *reinterpret_cast<const float2*>(R + kn);
                        fb[i][1] = *reinterpret_cast<const float2*>(R + 8 * INSZ + kn);
                        fb[i][2] = okhi ? *reinterpret_cast<const float2*>(R + kn + 8)
                                        : make_float2(0.0f, 0.0f);
                        fb[i][3] = okhi ? *reinterpret_cast<const float2*>(R + 8 * INSZ + kn + 8)
                                        : make_float2(0.0f, 0.0f);
                    }
                }
                uint2 bb[8];
                const uint2* Bf = reinterpret_cast<const uint2*>(sB) + ((sl * 64 + g) * 4 + tg);
#pragma unroll
                for (int j = 0; j < 8; j++) bb[j] = Bf[j * 32];
#pragma unroll
                for (int i = 0; i < 2; i++) {
                    uint32_t a0 = packbf(fa[i][0].x, fa[i][0].y);
                    uint32_t a1 = packbf(fa[i][1].x, fa[i][1].y);
                    uint32_t a2 = packbf(fa[i][2].x, fa[i][2].y);
                    uint32_t a3 = packbf(fa[i][3].x, fa[i][3].y);
#pragma unroll
                    for (int j = 0; j < 8; j++)
                        mma16816(acc[i][j], a0, a1, a2, a3, bb[j].x, bb[j].y);
                }
#pragma unroll
                for (int i = 0; i < 2; i++)
#pragma unroll
                    for (int q = 0; q < 4; q++) fa[i][q] = fb[i][q];
            }

            // epilogue + publish
#pragma unroll
            for (int i = 0; i < 2; i++) {
                int r0 = tile * TILE_M + w * 32 + i * 16 + g;
#pragma unroll
                for (int j = 0; j < 8; j++) {
                    int col = j * 8 + tg * 2;
                    *reinterpret_cast<float2*>(&d_xg[(size_t)r0 * NG + col]) =
                        make_float2(acc[i][j][0], acc[i][j][1]);
                    *reinterpret_cast<float2*>(&d_xg[(size_t)(r0 + 8) * NG + col]) =
                        make_float2(acc[i][j][2], acc[i][j][3]);
                }
            }
            __threadfence();
            __syncwarp();
            if (lane == 0) atomicAdd(&d_flag[tile], 1u);
        }
    } else {
        // ================= scan block (R8 scan + flag gating) =================
        if (tid >= 128) return;
        const int warp = tid >> 5;
        const int b = (blockIdx.x - GEMM_BLKS) * 4 + warp;
        const int l = lane & 15;
        const int side = b >> 8;

        float w1r[HID], w2r[HID];
#pragma unroll
        for (int k = 0; k < HID; k++) {
            w1r[k] = Whh[lane * HID + k];
            w2r[k] = Whh[(lane + 32) * HID + k];
        }
        const float biasA = b_ih[lane] + b_hh[lane];
        const float biasB = b_ih[lane + 32] + b_hh[lane + 32];

        float h = 0.0f, c = 0.0f;
        const float* xpA = d_xg + (size_t)b * NG + lane;
        const float* xpB = xpA + 32;

        wait4(0, side);
        wait4(4, side);
        float xa0 = xpA[0 * STRIDE_T], xb0 = xpB[0 * STRIDE_T];
        float xa1 = xpA[1 * STRIDE_T], xb1 = xpB[1 * STRIDE_T];
        float xa2 = xpA[2 * STRIDE_T], xb2 = xpB[2 * STRIDE_T];
        float xa3 = xpA[3 * STRIDE_T], xb3 = xpB[3 * STRIDE_T];

#define STEP(XA, XB, PIDX)                                              \
    {                                                                   \
        float g1 = XA + biasA;                                          \
        float g2 = XB + biasB;                                          \
        XA = xpA[(size_t)(PIDX) * STRIDE_T];                            \
        XB = xpB[(size_t)(PIDX) * STRIDE_T];                            \
        float hk[HID];                                                  \
        _Pragma("unroll")                                               \
        for (int k = 0; k < HID; k++) hk[k] = __shfl_sync(FULL, h, k);  \
        float s0 = g1, s1 = 0.0f, s2 = 0.0f, s3 = 0.0f;                 \
        float r0 = g2, r1 = 0.0f, r2 = 0.0f, r3 = 0.0f;                 \
        _Pragma("unroll")                                               \
        for (int k = 0; k < HID; k += 4) {                              \
            s0 = fmaf(hk[k],     w1r[k],     s0);                       \
            s1 = fmaf(hk[k + 1], w1r[k + 1], s1);                       \
            s2 = fmaf(hk[k + 2], w1r[k + 2], s2);                       \
            s3 = fmaf(hk[k + 3], w1r[k + 3], s3);                       \
            r0 = fmaf(hk[k],     w2r[k],     r0);                       \
            r1 = fmaf(hk[k + 1], w2r[k + 1], r1);                       \
            r2 = fmaf(hk[k + 2], w2r[k + 2], r2);                       \
            r3 = fmaf(hk[k + 3], w2r[k + 3], r3);                       \
        }                                                               \
        g1 = (s0 + s1) + (s2 + s3);                                     \
        g2 = (r0 + r1) + (r2 + r3);                                     \
        float fg = __shfl_sync(FULL, g1, l + 16);                       \
        float og = __shfl_sync(FULL, g2, l + 16);                       \
        float i_s = sigt(g1);                                           \
        float f_s = sigt(fg);                                           \
        float g_t = tanhapx(g2);                                        \
        c = fmaf(f_s, c, i_s * g_t);                                    \
        h = sigt(og) * tanhapx(c);                                      \
    }

        for (int t = 0; t < T_STEPS; t += 4) {
            const int p = t + 4;
            STEP(xa0, xb0, p + 0)
            STEP(xa1, xb1, p + 1)
            STEP(xa2, xb2, p + 2)
            STEP(xa3, xb3, p + 3)
            if (t + 8 < T_STEPS) wait4(t + 8, side);   // gate next group's prefetch
        }
#undef STEP

        float hk[HID];
#pragma unroll
        for (int k = 0; k < HID; k++) hk[k] = __shfl_sync(FULL, h, k);

        float wa[HID], wb[HID];
#pragma unroll
        for (int k = 0; k < HID; k++) {
            wa[k] = W1[lane * HID + k];
            wb[k] = W1[(lane + 32) * HID + k];
        }
        float za = b1[lane], zb = b1[lane + 32];
#pragma unroll
        for (int k = 0; k < HID; k++) {
            za = fmaf(hk[k], wa[k], za);
            zb = fmaf(hk[k], wb[k], zb);
        }
        za = fmaxf(za, 0.0f);
        zb = fmaxf(zb, 0.0f);
        float sacc = za * W2[lane] + zb * W2[lane + 32];
#pragma unroll
        for (int off = 16; off > 0; off >>= 1)
            sacc += __shfl_xor_sync(FULL, sacc, off);
        if (lane == 0) out[b] = 4.0f * sigx(sacc + b2[0]);
    }
}

// ---------------- launch ----------------
extern "C" void kernel_launch(void* const* d_in, const int* in_sizes, int n_in,
                              void* d_out, int out_size) {
    const float* x    = (const float*)d_in[0];
    const float* W_ih = (const float*)d_in[1];
    const float* W_hh = (const float*)d_in[2];
    const float* b_ih = (const float*)d_in[3];
    const float* b_hh = (const float*)d_in[4];
    const float* W1   = (const float*)d_in[5];
    const float* b1   = (const float*)d_in[6];
    const float* W2   = (const float*)d_in[7];
    const float* b2   = (const float*)d_in[8];
    float* out = (float*)d_out;

    zero_flags<<<4, 256>>>();
    fused_kernel<<<GEMM_BLKS + SCAN_BLKS, 256>>>(x, W_ih, W_hh, b_ih, b_hh,
                                                 W1, b1, W2, b2, out);
}

// round 13
// speedup vs baseline: 1.3830x; 1.3830x over previous
#include <cuda_runtime.h>
#include <cuda_bf16.h>
#include <cstdint>

#define T_STEPS 512
#define BATCH   512
#define INSZ    300
#define HID     16
#define NG      64
#define NROWS   (T_STEPS*BATCH)     // 262144
#define TILE_M  128
#define NTILES  (NROWS/TILE_M)      // 2048
#define GRID_G  296                 // 2 blocks per SM
#define STRIDE_T (BATCH*NG)
#define ASTRIDE 72                  // fp32 row stride in A smem

#define A_ELEMS (TILE_M*ASTRIDE)    // 9216 floats per buffer
#define B_WORDS (19*64*8)           // 9728 uint32 (bf16x2 pairs)
#define SMEM_BYTES (2*A_ELEMS*4 + B_WORDS*4)   // 112640

__device__ float d_xg[(size_t)(NROWS + 8 * BATCH) * NG];

// ---------------- asm helpers ----------------
__device__ __forceinline__ uint32_t smem_u32(const void* p) {
    uint32_t a;
    asm("{ .reg .u64 t; cvta.to.shared.u64 t, %1; cvt.u32.u64 %0, t; }" : "=r"(a) : "l"(p));
    return a;
}
__device__ __forceinline__ void cp16(uint32_t sa, const float* g) {
    asm volatile("cp.async.cg.shared.global [%0], [%1], 16;" :: "r"(sa), "l"(g) : "memory");
}
#define CP_COMMIT() asm volatile("cp.async.commit_group;" ::: "memory")
#define CP_WAIT1()  asm volatile("cp.async.wait_group 1;" ::: "memory")

__device__ __forceinline__ void mma16816(float* d, uint32_t a0, uint32_t a1, uint32_t a2,
                                         uint32_t a3, uint32_t b0, uint32_t b1) {
    asm volatile(
        "mma.sync.aligned.m16n8k16.row.col.f32.bf16.bf16.f32 "
        "{%0,%1,%2,%3}, {%4,%5,%6,%7}, {%8,%9}, {%0,%1,%2,%3};"
        : "+f"(d[0]), "+f"(d[1]), "+f"(d[2]), "+f"(d[3])
        : "r"(a0), "r"(a1), "r"(a2), "r"(a3), "r"(b0), "r"(b1));
}
__device__ __forceinline__ uint32_t packbf(float lo, float hi) {
    __nv_bfloat162 p = __floats2bfloat162_rn(lo, hi);
    return *reinterpret_cast<uint32_t*>(&p);
}

// copy one 64-col K-chunk of a 128-row tile (256 threads)
__device__ __forceinline__ void cp_chunk(const float* __restrict__ x, uint32_t abase,
                                         int tile, int ch) {
    const int tid = threadIdx.x;
    const int j  = tid & 15;
    const int rr = tid >> 4;          // 0..15
    const int c0 = ch * 64;
    const int jmax = (ch == 4) ? 11 : 16;
#pragma unroll
    for (int p = 0; p < 8; p++) {
        int r = p * 16 + rr;
        uint32_t soff = abase + ((uint32_t)(r * ASTRIDE) + 4u * (uint32_t)j) * 4u;
        if (j < jmax) {
            cp16(soff, x + (size_t)(tile * TILE_M + r) * INSZ + c0 + 4 * j);
        } else if (ch == 4 && j == 11) {
            asm volatile("st.shared.v4.u32 [%0], {%1,%1,%1,%1};" :: "r"(soff), "r"(0u) : "memory");
        }
    }
    CP_COMMIT();
}

// ---------------- GEMM: d_xg = x @ W_ih^T  (bf16 mma.sync, TILE_M=128, occ 2) ----------------
__global__ void __launch_bounds__(256, 2)
gemm_kernel(const float* __restrict__ x, const float* __restrict__ W) {
    extern __shared__ float sm[];
    float* sA0 = sm;
    float* sA1 = sm + A_ELEMS;
    uint32_t* sB = reinterpret_cast<uint32_t*>(sm + 2 * A_ELEMS);
    const uint32_t sbase = smem_u32(sm);
    const uint32_t aB[2] = { sbase, sbase + A_ELEMS * 4u };
    float* sAp[2] = { sA0, sA1 };

    const int tid  = threadIdx.x;
    const int w    = tid >> 5;        // 0..7 -> m16 tile w
    const int lane = tid & 31;
    const int g    = lane >> 2;
    const int tg   = lane & 3;

    cp_chunk(x, aB[0], blockIdx.x, 0);

    // B fill (once): W[n][k] fp32 -> bf16x2 fragment-pair layout
    for (int i = tid; i < 19 * 64 * 4; i += 256) {
        int s = i >> 8;
        int n = (i >> 2) & 63;
        int t = i & 3;
        int k0 = 16 * s + 2 * t;
        const float* Wn = W + (size_t)n * INSZ;
        float v0 = (k0     < INSZ) ? Wn[k0]     : 0.0f;
        float v1 = (k0 + 1 < INSZ) ? Wn[k0 + 1] : 0.0f;
        float v2 = (k0 + 8 < INSZ) ? Wn[k0 + 8] : 0.0f;
        float v3 = (k0 + 9 < INSZ) ? Wn[k0 + 9] : 0.0f;
        int base = ((s * 64 + n) * 4 + t) * 2;
        sB[base]     = packbf(v0, v1);
        sB[base + 1] = packbf(v2, v3);
    }
    __syncthreads();

    int buf = 0;
    for (int tile = blockIdx.x; tile < NTILES; tile += GRID_G) {
        float acc[8][4];
#pragma unroll
        for (int j = 0; j < 8; j++)
#pragma unroll
            for (int r = 0; r < 4; r++) acc[j][r] = 0.0f;

        for (int ch = 0; ch < 5; ch++) {
            int ntile = tile, nch = ch + 1;
            if (nch == 5) { ntile = tile + GRID_G; nch = 0; }
            if (ntile < NTILES) cp_chunk(x, aB[buf ^ 1], ntile, nch);
            else CP_COMMIT();
            CP_WAIT1();
            __syncthreads();

            const float* A = sAp[buf];
            const int nsl = (ch == 4) ? 3 : 4;
            for (int sl = 0; sl < nsl; sl++) {
                const int s = ch * 4 + sl;
                uint2 bb[8];
                const uint2* Bf = reinterpret_cast<const uint2*>(sB)
                                + ((s * 64 + g) * 4 + tg);
#pragma unroll
                for (int j = 0; j < 8; j++) bb[j] = Bf[j * 32];

                const int r0 = w * 16 + g;
                const float* Ab = A + r0 * ASTRIDE + sl * 16 + 2 * tg;
                float2 f0 = *reinterpret_cast<const float2*>(Ab);
                float2 f1 = *reinterpret_cast<const float2*>(Ab + 8 * ASTRIDE);
                float2 f2 = *reinterpret_cast<const float2*>(Ab + 8);
                float2 f3 = *reinterpret_cast<const float2*>(Ab + 8 * ASTRIDE + 8);
                uint32_t a0 = packbf(f0.x, f0.y);
                uint32_t a1 = packbf(f1.x, f1.y);
                uint32_t a2 = packbf(f2.x, f2.y);
                uint32_t a3 = packbf(f3.x, f3.y);
#pragma unroll
                for (int j = 0; j < 8; j++)
                    mma16816(acc[j], a0, a1, a2, a3, bb[j].x, bb[j].y);
            }
            __syncthreads();
            buf ^= 1;
        }

        {
            int r0 = tile * TILE_M + w * 16 + g;
#pragma unroll
            for (int j = 0; j < 8; j++) {
                int col = j * 8 + tg * 2;
                *reinterpret_cast<float2*>(&d_xg[(size_t)r0 * NG + col]) =
                    make_float2(acc[j][0], acc[j][1]);
                *reinterpret_cast<float2*>(&d_xg[(size_t)(r0 + 8) * NG + col]) =
                    make_float2(acc[j][2], acc[j][3]);
            }
        }
    }
}

// ---------------- scan (R8 form, unchanged) ----------------
__device__ __forceinline__ float tanhapx(float x) {
    float y;
    asm("tanh.approx.f32 %0, %1;" : "=f"(y) : "f"(x));
    return y;
}
__device__ __forceinline__ float sigt(float x) {
    return fmaf(tanhapx(0.5f * x), 0.5f, 0.5f);
}
__device__ __forceinline__ float sigx(float x) {
    float e = __expf(-x);
    return __fdividef(1.0f, 1.0f + e);
}

__global__ void __launch_bounds__(128, 1)
scan_kernel(const float* __restrict__ Whh,
            const float* __restrict__ b_ih, const float* __restrict__ b_hh,
            const float* __restrict__ W1, const float* __restrict__ b1,
            const float* __restrict__ W2, const float* __restrict__ b2,
            float* __restrict__ out) {
    const int warp = threadIdx.x >> 5;
    const int lane = threadIdx.x & 31;
    const int b = blockIdx.x * 4 + warp;
    const int l = lane & 15;
    const unsigned FULL = 0xffffffffu;

    float w1r[HID], w2r[HID];
#pragma unroll
    for (int k = 0; k < HID; k++) {
        w1r[k] = Whh[lane * HID + k];
        w2r[k] = Whh[(lane + 32) * HID + k];
    }
    const float biasA = b_ih[lane] + b_hh[lane];
    const float biasB = b_ih[lane + 32] + b_hh[lane + 32];

    float h = 0.0f, c = 0.0f;
    const float* xpA = d_xg + (size_t)b * NG + lane;
    const float* xpB = xpA + 32;

    float xa0 = xpA[0 * STRIDE_T], xb0 = xpB[0 * STRIDE_T];
    float xa1 = xpA[1 * STRIDE_T], xb1 = xpB[1 * STRIDE_T];
    float xa2 = xpA[2 * STRIDE_T], xb2 = xpB[2 * STRIDE_T];
    float xa3 = xpA[3 * STRIDE_T], xb3 = xpB[3 * STRIDE_T];

#define STEP(XA, XB, PIDX)                                              \
    {                                                                   \
        float g1 = XA + biasA;                                          \
        float g2 = XB + biasB;                                          \
        XA = xpA[(size_t)(PIDX) * STRIDE_T];                            \
        XB = xpB[(size_t)(PIDX) * STRIDE_T];                            \
        float hk[HID];                                                  \
        _Pragma("unroll")                                               \
        for (int k = 0; k < HID; k++) hk[k] = __shfl_sync(FULL, h, k);  \
        float s0 = g1, s1 = 0.0f, s2 = 0.0f, s3 = 0.0f;                 \
        float r0 = g2, r1 = 0.0f, r2 = 0.0f, r3 = 0.0f;                 \
        _Pragma("unroll")                                               \
        for (int k = 0; k < HID; k += 4) {                              \
            s0 = fmaf(hk[k],     w1r[k],     s0);                       \
            s1 = fmaf(hk[k + 1], w1r[k + 1], s1);                       \
            s2 = fmaf(hk[k + 2], w1r[k + 2], s2);                       \
            s3 = fmaf(hk[k + 3], w1r[k + 3], s3);                       \
            r0 = fmaf(hk[k],     w2r[k],     r0);                       \
            r1 = fmaf(hk[k + 1], w2r[k + 1], r1);                       \
            r2 = fmaf(hk[k + 2], w2r[k + 2], r2);                       \
            r3 = fmaf(hk[k + 3], w2r[k + 3], r3);                       \
        }                                                               \
        g1 = (s0 + s1) + (s2 + s3);                                     \
        g2 = (r0 + r1) + (r2 + r3);                                     \
        float fg = __shfl_sync(FULL, g1, l + 16);                       \
        float og = __shfl_sync(FULL, g2, l + 16);                       \
        float i_s = sigt(g1);                                           \
        float f_s = sigt(fg);                                           \
        float g_t = tanhapx(g2);                                        \
        c = fmaf(f_s, c, i_s * g_t);                                    \
        h = sigt(og) * tanhapx(c);                                      \
    }

    for (int t = 0; t < T_STEPS; t += 4) {
        const int p = t + 4;
        STEP(xa0, xb0, p + 0)
        STEP(xa1, xb1, p + 1)
        STEP(xa2, xb2, p + 2)
        STEP(xa3, xb3, p + 3)
    }
#undef STEP

    float hk[HID];
#pragma unroll
    for (int k = 0; k < HID; k++) hk[k] = __shfl_sync(FULL, h, k);

    float wa[HID], wb[HID];
#pragma unroll
    for (int k = 0; k < HID; k++) {
        wa[k] = W1[lane * HID + k];
        wb[k] = W1[(lane + 32) * HID + k];
    }
    float za = b1[lane], zb = b1[lane + 32];
#pragma unroll
    for (int k = 0; k < HID; k++) {
        za = fmaf(hk[k], wa[k], za);
        zb = fmaf(hk[k], wb[k], zb);
    }
    za = fmaxf(za, 0.0f);
    zb = fmaxf(zb, 0.0f);
    float sacc = za * W2[lane] + zb * W2[lane + 32];
#pragma unroll
    for (int off = 16; off > 0; off >>= 1)
        sacc += __shfl_xor_sync(FULL, sacc, off);
    if (lane == 0) out[b] = 4.0f * sigx(sacc + b2[0]);
}

// ---------------- dummy: pads the launch pattern so ncu (-s 5) profiles the GEMM ----------------
__global__ void dummy_kernel() {}

// ---------------- launch ----------------
extern "C" void kernel_launch(void* const* d_in, const int* in_sizes, int n_in,
                              void* d_out, int out_size) {
    const float* x    = (const float*)d_in[0];
    const float* W_ih = (const float*)d_in[1];
    const float* W_hh = (const float*)d_in[2];
    const float* b_ih = (const float*)d_in[3];
    const float* b_hh = (const float*)d_in[4];
    const float* W1   = (const float*)d_in[5];
    const float* b1   = (const float*)d_in[6];
    const float* W2   = (const float*)d_in[7];
    const float* b2   = (const float*)d_in[8];
    float* out = (float*)d_out;

    cudaFuncSetAttribute(gemm_kernel, cudaFuncAttributeMaxDynamicSharedMemorySize, SMEM_BYTES);
    // pattern length 7; index 5 (ncu -s 5 -c 1) == gemm_kernel
    dummy_kernel<<<1, 32>>>();
    dummy_kernel<<<1, 32>>>();
    dummy_kernel<<<1, 32>>>();
    dummy_kernel<<<1, 32>>>();
    dummy_kernel<<<1, 32>>>();
    gemm_kernel<<<GRID_G, 256, SMEM_BYTES>>>(x, W_ih);
    scan_kernel<<<128, 128>>>(W_hh, b_ih, b_hh, W1, b1, W2, b2, out);
}